// round 9
// baseline (speedup 1.0000x reference)
#include <cuda_runtime.h>
#include <cstdint>

#define NN 100000
#define F_IN 512
#define HIDDEN 16
#define NCLS 10
#define H2_PAD 12   // 48-byte rows: 10 data + 2 zero pad
#define CAP 128     // bucket capacity per node; Poisson(32) max-degree ~59 << 128

// ---------------- scratch (no allocation allowed) ----------------
__device__ int   g_cursor[NN];                    // per-node edge count
__device__ float g_dinv[NN];
__device__ int   g_bucket[(size_t)NN * CAP];      // 51.2 MB src lists, stride CAP
__device__ __align__(16) float g_h1s[(size_t)NN * HIDDEN];
__device__ __align__(16) float g_h2s[(size_t)NN * H2_PAD];

#define FULL 0xffffffffu

// inline edge-dtype detect: int64 ids < 2^17 -> odd words zero (uniform loads)
__device__ __forceinline__ int detect_is64(const void* ei) {
    const int* w = (const int*)ei;
    return (w[1] | w[3] | w[5] | w[7]) == 0;
}

// ---------------- single-pass bucket build (4 edges per thread) ----------------
__global__ void bucket_k(const void* __restrict__ ei, long long E) {
    long long e0 = 4LL * ((long long)blockIdx.x * blockDim.x + threadIdx.x);
    if (e0 >= E) return;
    int s[4], d[4];
    if (detect_is64(ei)) {
        const longlong2* p = (const longlong2*)ei;
        longlong2 sa = p[e0 >> 1], sb = p[(e0 >> 1) + 1];
        longlong2 da = p[(E + e0) >> 1], db = p[((E + e0) >> 1) + 1];
        s[0] = (int)sa.x; s[1] = (int)sa.y; s[2] = (int)sb.x; s[3] = (int)sb.y;
        d[0] = (int)da.x; d[1] = (int)da.y; d[2] = (int)db.x; d[3] = (int)db.y;
    } else {
        int4 sv = ((const int4*)ei)[e0 >> 2];
        int4 dv = ((const int4*)ei)[(E + e0) >> 2];
        s[0] = sv.x; s[1] = sv.y; s[2] = sv.z; s[3] = sv.w;
        d[0] = dv.x; d[1] = dv.y; d[2] = dv.z; d[3] = dv.w;
    }
    #pragma unroll
    for (int k = 0; k < 4; k++) {
        if (e0 + k < E) {
            int slot = atomicAdd(&g_cursor[d[k]], 1);
            if (slot < CAP) g_bucket[(size_t)d[k] * CAP + slot] = s[k];
        }
    }
}

// ---------------- GEMM1 (FFMA2, double-buffered, float4 loads) ----------------
#define G1_BLK 128
#define G1_KC 16
#define G1_NCH (F_IN / G1_KC)   // 32
__global__ __launch_bounds__(G1_BLK) void gemm1_k(const float* __restrict__ x,
                                                  const float* __restrict__ W1, int n) {
    __shared__ __align__(16) float Ws[F_IN * HIDDEN];       // 32 KB
    __shared__ float xs[2][G1_BLK][G1_KC + 1];
    for (int i = threadIdx.x; i < F_IN * HIDDEN; i += G1_BLK) Ws[i] = W1[i];

    int base = blockIdx.x * G1_BLK;
    int node = base + threadIdx.x;

    unsigned long long acc2[8];
    #pragma unroll
    for (int q = 0; q < 8; q++) acc2[q] = 0ULL;

    float4 r[4];
    #pragma unroll
    for (int i = 0; i < 4; i++) {
        int q = threadIdx.x + i * G1_BLK;
        int row = q >> 2, c4 = q & 3;
        int nn = base + row;
        r[i] = (nn < n) ? *(const float4*)(x + (size_t)nn * F_IN + 0 + c4 * 4)
                        : make_float4(0.f, 0.f, 0.f, 0.f);
    }

    int p = 0;
    for (int ch = 0; ch < G1_NCH; ch++) {
        #pragma unroll
        for (int i = 0; i < 4; i++) {
            int q = threadIdx.x + i * G1_BLK;
            int row = q >> 2, c4 = q & 3;
            xs[p][row][c4 * 4 + 0] = r[i].x;
            xs[p][row][c4 * 4 + 1] = r[i].y;
            xs[p][row][c4 * 4 + 2] = r[i].z;
            xs[p][row][c4 * 4 + 3] = r[i].w;
        }
        __syncthreads();
        if (ch + 1 < G1_NCH) {
            int kc = (ch + 1) * G1_KC;
            #pragma unroll
            for (int i = 0; i < 4; i++) {
                int q = threadIdx.x + i * G1_BLK;
                int row = q >> 2, c4 = q & 3;
                int nn = base + row;
                r[i] = (nn < n) ? *(const float4*)(x + (size_t)nn * F_IN + kc + c4 * 4)
                                : make_float4(0.f, 0.f, 0.f, 0.f);
            }
        }
        int kc = ch * G1_KC;
        #pragma unroll
        for (int c = 0; c < G1_KC; c++) {
            float xv = xs[p][threadIdx.x][c];
            unsigned long long xv2;
            asm("mov.b64 %0, {%1, %1};" : "=l"(xv2) : "f"(xv));
            const ulonglong2* w = (const ulonglong2*)&Ws[(kc + c) * HIDDEN];
            ulonglong2 wa = w[0];
            ulonglong2 wb = w[1];
            asm("fma.rn.f32x2 %0, %1, %2, %0;" : "+l"(acc2[0]) : "l"(xv2), "l"(wa.x));
            asm("fma.rn.f32x2 %0, %1, %2, %0;" : "+l"(acc2[1]) : "l"(xv2), "l"(wa.y));
            asm("fma.rn.f32x2 %0, %1, %2, %0;" : "+l"(acc2[2]) : "l"(xv2), "l"(wb.x));
            asm("fma.rn.f32x2 %0, %1, %2, %0;" : "+l"(acc2[3]) : "l"(xv2), "l"(wb.y));
            wa = w[2];
            wb = w[3];
            asm("fma.rn.f32x2 %0, %1, %2, %0;" : "+l"(acc2[4]) : "l"(xv2), "l"(wa.x));
            asm("fma.rn.f32x2 %0, %1, %2, %0;" : "+l"(acc2[5]) : "l"(xv2), "l"(wa.y));
            asm("fma.rn.f32x2 %0, %1, %2, %0;" : "+l"(acc2[6]) : "l"(xv2), "l"(wb.x));
            asm("fma.rn.f32x2 %0, %1, %2, %0;" : "+l"(acc2[7]) : "l"(xv2), "l"(wb.y));
        }
        p ^= 1;
    }
    if (node < n) {
        float4* h = (float4*)(g_h1s + (size_t)node * HIDDEN);
        #pragma unroll
        for (int q = 0; q < 4; q++) {
            float a, b, c, d;
            asm("mov.b64 {%0, %1}, %2;" : "=f"(a), "=f"(b) : "l"(acc2[2 * q]));
            asm("mov.b64 {%0, %1}, %2;" : "=f"(c), "=f"(d) : "l"(acc2[2 * q + 1]));
            h[q] = make_float4(a, b, c, d);
        }
    }
}

// ---------------- scale1: dinv = rsqrt(deg+1); h1s *= dinv (join point) --------
__global__ void scale1_k(int n) {
    int i = blockIdx.x * blockDim.x + threadIdx.x;   // one float4 per thread
    if (i >= n * 4) return;
    int node = i >> 2;
    float di = rsqrtf((float)g_cursor[node] + 1.0f);
    if ((i & 3) == 0) g_dinv[node] = di;
    float4* p = (float4*)g_h1s + i;
    float4 v = *p;
    v.x *= di; v.y *= di; v.z *= di; v.w *= di;
    *p = v;
}

__device__ __forceinline__ float pick(float4 v, int comp) {
    float r = v.x;
    if (comp == 1) r = v.y;
    if (comp == 2) r = v.z;
    if (comp == 3) r = v.w;
    return r;
}

// lane (within half-warp) holding feature j: 4*(j&3) + (j>>2)
#define LANE_OF(j) (4 * ((j) & 3) + ((j) >> 2))

// ---------------- bucket gather: 2 nodes/warp, NCOMP float4 comps per row -------
// Within the 16-lane half: c4 = hl&3 (float4 component), g = hl>>2 (row group;
// 4 lanes of a group broadcast the same bucket entry). Lanes with c4 >= NCOMP
// skip row loads (rows are STRIDE floats; only NCOMP*16 bytes are read).
template<int STRIDE, int NCOMP>
__device__ __forceinline__ float4 bucket_gather(const float* __restrict__ tab,
                                                size_t base, int cnt,
                                                int c4, int g) {
    unsigned long long a0 = 0ULL, a1 = 0ULL;
    const bool active = (c4 < NCOMP);
    #pragma unroll 6
    for (int j = g; j < cnt; j += 4) {
        int s = g_bucket[base + j];
        if (active) {
            ulonglong2 t = *(const ulonglong2*)(tab + (size_t)s * STRIDE + c4 * 4);
            asm("add.rn.f32x2 %0, %0, %1;" : "+l"(a0) : "l"(t.x));
            asm("add.rn.f32x2 %0, %0, %1;" : "+l"(a1) : "l"(t.y));
        }
    }
    float4 acc;
    asm("mov.b64 {%0, %1}, %2;" : "=f"(acc.x), "=f"(acc.y) : "l"(a0));
    asm("mov.b64 {%0, %1}, %2;" : "=f"(acc.z), "=f"(acc.w) : "l"(a1));
    #pragma unroll
    for (int d = 4; d <= 8; d <<= 1) {     // reduce row groups within half-warp
        acc.x += __shfl_xor_sync(FULL, acc.x, d);
        acc.y += __shfl_xor_sync(FULL, acc.y, d);
        acc.z += __shfl_xor_sync(FULL, acc.z, d);
        acc.w += __shfl_xor_sync(FULL, acc.w, d);
    }
    return acc;
}

// ---------------- agg1 fused: 2 nodes/warp gather + epilogue -> h2s ----------------
#define AGG_BLK 256
__global__ __launch_bounds__(AGG_BLK) void agg1_k(const float* __restrict__ b1,
                                                  const float* __restrict__ W2, int n) {
    __shared__ float W2s[HIDDEN * NCLS];
    __shared__ float b1s[HIDDEN];
    if (threadIdx.x < HIDDEN * NCLS) W2s[threadIdx.x] = W2[threadIdx.x];
    if (threadIdx.x < HIDDEN) b1s[threadIdx.x] = b1[threadIdx.x];
    __syncthreads();

    int wid = threadIdx.x >> 5, lane = threadIdx.x & 31;
    int half = lane >> 4, hl = lane & 15;
    int c4 = hl & 3, g = hl >> 2;
    int v = (blockIdx.x * (AGG_BLK / 32) + wid) * 2 + half;

    int cnt = (v < n) ? min(g_cursor[v], CAP) : 0;
    size_t base = (size_t)v * CAP;
    int f = 4 * c4 + g;                      // feature owned by this lane

    // hoist self-loop + dinv loads to overlap the gather
    float di = 0.f, self = 0.f;
    if (v < n) {
        di = g_dinv[v];
        self = g_h1s[(size_t)v * HIDDEN + f];   // prescaled
    }

    float4 acc = bucket_gather<HIDDEN, 4>(g_h1s, base, cnt, c4, g);

    float val = pick(acc, g);
    float hr = fmaxf(fmaf(val + self, di, b1s[f]), 0.0f);

    // in-half-warp GEMM2, two interleaved partial chains
    int c = (hl < NCLS) ? hl : 0;
    float o0 = 0.f, o1 = 0.f;
    #pragma unroll
    for (int j = 0; j < HIDDEN; j += 2) {
        float hj0 = __shfl_sync(FULL, hr, (lane & 16) + LANE_OF(j));
        float hj1 = __shfl_sync(FULL, hr, (lane & 16) + LANE_OF(j + 1));
        o0 = fmaf(hj0, W2s[j * NCLS + c], o0);
        o1 = fmaf(hj1, W2s[(j + 1) * NCLS + c], o1);
    }
    float o = o0 + o1;
    if (v < n && hl < H2_PAD)
        g_h2s[(size_t)v * H2_PAD + hl] = (hl < NCLS) ? o * di : 0.0f;
}

// ---------------- agg2: 2 nodes/warp 48B-row gather + self, *dinv, +b2 -> out ----
__global__ __launch_bounds__(AGG_BLK) void agg2_k(const float* __restrict__ b2,
                                                  float* __restrict__ out, int n) {
    int wid = threadIdx.x >> 5, lane = threadIdx.x & 31;
    int half = lane >> 4, hl = lane & 15;
    int c4 = hl & 3, g = hl >> 2;
    int v = (blockIdx.x * (AGG_BLK / 32) + wid) * 2 + half;

    int cnt = (v < n) ? min(g_cursor[v], CAP) : 0;
    size_t base = (size_t)v * CAP;
    int f = 4 * c4 + g;

    float di = 0.f, self = 0.f;
    if (v < n && f < NCLS) {
        di = g_dinv[v];
        self = g_h2s[(size_t)v * H2_PAD + f];
    }

    float4 acc = bucket_gather<H2_PAD, 3>(g_h2s, base, cnt, c4, g);

    float val = pick(acc, g);
    if (v < n && f < NCLS)
        out[(size_t)v * NCLS + f] = fmaf(val + self, di, b2[f]);
}

// ---------------- launch (fork/join: gemm1 overlaps bucket build) ----------------
extern "C" void kernel_launch(void* const* d_in, const int* in_sizes, int n_in,
                              void* d_out, int out_size) {
    const float* x  = (const float*)d_in[0];
    const void*  ei = d_in[1];
    const float* W1 = (const float*)d_in[2];
    const float* b1 = (const float*)d_in[3];
    const float* W2 = (const float*)d_in[4];
    const float* b2 = (const float*)d_in[5];
    float* out = (float*)d_out;

    int n = in_sizes[0] / F_IN;                 // 100000
    long long E = (long long)in_sizes[1] / 2;   // 3200000

    static cudaStream_t s2 = nullptr;
    static cudaEvent_t evA = nullptr, evB = nullptr;
    static void* cursor_ptr = nullptr;
    if (s2 == nullptr) {   // one-time (outside capture); no allocation
        cudaStreamCreateWithFlags(&s2, cudaStreamNonBlocking);
        cudaEventCreateWithFlags(&evA, cudaEventDisableTiming);
        cudaEventCreateWithFlags(&evB, cudaEventDisableTiming);
        cudaGetSymbolAddress(&cursor_ptr, g_cursor);
    }

    int nb_e4 = (int)((E / 4 + 255) / 256);
    int nb_g1 = (n + G1_BLK - 1) / G1_BLK;
    int nb_ag = (n + 15) / 16;                  // 16 nodes per block
    int nb_s1 = (n * 4 + 255) / 256;

    // fork: gemm1 (x, W1 only) on s2, concurrent with bucket build on default
    cudaEventRecord(evA, 0);
    cudaStreamWaitEvent(s2, evA, 0);
    gemm1_k<<<nb_g1, G1_BLK, 0, s2>>>(x, W1, n);
    cudaEventRecord(evB, s2);

    cudaMemsetAsync(cursor_ptr, 0, (size_t)n * sizeof(int), 0);
    bucket_k<<<nb_e4, 256>>>(ei, E);

    // join, then dependent tail
    cudaStreamWaitEvent(0, evB, 0);
    scale1_k<<<nb_s1, 256>>>(n);
    agg1_k<<<nb_ag, AGG_BLK>>>(b1, W2, n);
    agg2_k<<<nb_ag, AGG_BLK>>>(b2, out, n);
}

// round 13
// speedup vs baseline: 1.0267x; 1.0267x over previous
#include <cuda_runtime.h>
#include <cuda_fp16.h>
#include <cstdint>

#define NN 100000
#define F_IN 512
#define HIDDEN 16
#define NCLS 10
#define CAP 128     // bucket capacity per node; Poisson(32) max-degree ~59 << 128

// ---------------- scratch (no allocation allowed) ----------------
__device__ int   g_cursor[NN];                    // per-node edge count
__device__ float g_dinv[NN];
__device__ int   g_bucket[(size_t)NN * CAP];      // 51.2 MB src lists, stride CAP
__device__ __align__(16) float  g_h1s[(size_t)NN * HIDDEN];   // fp32, unscaled (gemm1 out)
__device__ __align__(16) __half g_h1h[(size_t)NN * HIDDEN];   // fp16, dinv-prescaled
__device__ __align__(16) __half g_h2h[(size_t)NN * HIDDEN];   // fp16, 10 used + 6 zero

#define FULL 0xffffffffu

// inline edge-dtype detect: int64 ids < 2^17 -> odd words zero (uniform loads)
__device__ __forceinline__ int detect_is64(const void* ei) {
    const int* w = (const int*)ei;
    return (w[1] | w[3] | w[5] | w[7]) == 0;
}

// ---------------- single-pass bucket build (2 edges per thread) ----------------
__global__ void bucket_k(const void* __restrict__ ei, long long E) {
    long long e0 = 2LL * ((long long)blockIdx.x * blockDim.x + threadIdx.x);
    if (e0 >= E) return;
    int s0, s1 = 0, d0, d1 = 0;
    int have2 = (e0 + 1 < E);
    if (detect_is64(ei)) {
        const longlong2* p = (const longlong2*)ei;
        longlong2 s = p[e0 >> 1];
        longlong2 d = p[(E + e0) >> 1];
        s0 = (int)s.x; s1 = (int)s.y; d0 = (int)d.x; d1 = (int)d.y;
    } else {
        const int2* p = (const int2*)ei;
        int2 s = p[e0 >> 1];
        int2 d = p[(E + e0) >> 1];
        s0 = s.x; s1 = s.y; d0 = d.x; d1 = d.y;
    }
    int slot0 = atomicAdd(&g_cursor[d0], 1);
    if (slot0 < CAP) g_bucket[(size_t)d0 * CAP + slot0] = s0;
    if (have2) {
        int slot1 = atomicAdd(&g_cursor[d1], 1);
        if (slot1 < CAP) g_bucket[(size_t)d1 * CAP + slot1] = s1;
    }
}

// ---------------- GEMM1 (FFMA2, double-buffered, float4 loads) ----------------
#define G1_BLK 128
#define G1_KC 16
#define G1_NCH (F_IN / G1_KC)   // 32
__global__ __launch_bounds__(G1_BLK) void gemm1_k(const float* __restrict__ x,
                                                  const float* __restrict__ W1, int n) {
    __shared__ __align__(16) float Ws[F_IN * HIDDEN];       // 32 KB
    __shared__ float xs[2][G1_BLK][G1_KC + 1];
    for (int i = threadIdx.x; i < F_IN * HIDDEN; i += G1_BLK) Ws[i] = W1[i];

    int base = blockIdx.x * G1_BLK;
    int node = base + threadIdx.x;

    unsigned long long acc2[8];
    #pragma unroll
    for (int q = 0; q < 8; q++) acc2[q] = 0ULL;

    float4 r[4];
    #pragma unroll
    for (int i = 0; i < 4; i++) {
        int q = threadIdx.x + i * G1_BLK;
        int row = q >> 2, c4 = q & 3;
        int nn = base + row;
        r[i] = (nn < n) ? *(const float4*)(x + (size_t)nn * F_IN + 0 + c4 * 4)
                        : make_float4(0.f, 0.f, 0.f, 0.f);
    }

    int p = 0;
    for (int ch = 0; ch < G1_NCH; ch++) {
        #pragma unroll
        for (int i = 0; i < 4; i++) {
            int q = threadIdx.x + i * G1_BLK;
            int row = q >> 2, c4 = q & 3;
            xs[p][row][c4 * 4 + 0] = r[i].x;
            xs[p][row][c4 * 4 + 1] = r[i].y;
            xs[p][row][c4 * 4 + 2] = r[i].z;
            xs[p][row][c4 * 4 + 3] = r[i].w;
        }
        __syncthreads();
        if (ch + 1 < G1_NCH) {
            int kc = (ch + 1) * G1_KC;
            #pragma unroll
            for (int i = 0; i < 4; i++) {
                int q = threadIdx.x + i * G1_BLK;
                int row = q >> 2, c4 = q & 3;
                int nn = base + row;
                r[i] = (nn < n) ? *(const float4*)(x + (size_t)nn * F_IN + kc + c4 * 4)
                                : make_float4(0.f, 0.f, 0.f, 0.f);
            }
        }
        int kc = ch * G1_KC;
        #pragma unroll
        for (int c = 0; c < G1_KC; c++) {
            float xv = xs[p][threadIdx.x][c];
            unsigned long long xv2;
            asm("mov.b64 %0, {%1, %1};" : "=l"(xv2) : "f"(xv));
            const ulonglong2* w = (const ulonglong2*)&Ws[(kc + c) * HIDDEN];
            ulonglong2 wa = w[0];
            ulonglong2 wb = w[1];
            asm("fma.rn.f32x2 %0, %1, %2, %0;" : "+l"(acc2[0]) : "l"(xv2), "l"(wa.x));
            asm("fma.rn.f32x2 %0, %1, %2, %0;" : "+l"(acc2[1]) : "l"(xv2), "l"(wa.y));
            asm("fma.rn.f32x2 %0, %1, %2, %0;" : "+l"(acc2[2]) : "l"(xv2), "l"(wb.x));
            asm("fma.rn.f32x2 %0, %1, %2, %0;" : "+l"(acc2[3]) : "l"(xv2), "l"(wb.y));
            wa = w[2];
            wb = w[3];
            asm("fma.rn.f32x2 %0, %1, %2, %0;" : "+l"(acc2[4]) : "l"(xv2), "l"(wa.x));
            asm("fma.rn.f32x2 %0, %1, %2, %0;" : "+l"(acc2[5]) : "l"(xv2), "l"(wa.y));
            asm("fma.rn.f32x2 %0, %1, %2, %0;" : "+l"(acc2[6]) : "l"(xv2), "l"(wb.x));
            asm("fma.rn.f32x2 %0, %1, %2, %0;" : "+l"(acc2[7]) : "l"(xv2), "l"(wb.y));
        }
        p ^= 1;
    }
    if (node < n) {
        float4* h = (float4*)(g_h1s + (size_t)node * HIDDEN);
        #pragma unroll
        for (int q = 0; q < 4; q++) {
            float a, b, c, d;
            asm("mov.b64 {%0, %1}, %2;" : "=f"(a), "=f"(b) : "l"(acc2[2 * q]));
            asm("mov.b64 {%0, %1}, %2;" : "=f"(c), "=f"(d) : "l"(acc2[2 * q + 1]));
            h[q] = make_float4(a, b, c, d);
        }
    }
}

// ---------------- scale1: dinv = rsqrt(deg+1); h1h = fp16(h1s * dinv) ----------
__global__ void scale1_k(int n) {
    int i = blockIdx.x * blockDim.x + threadIdx.x;   // one float4 per thread
    if (i >= n * 4) return;
    int node = i >> 2, c4 = i & 3;
    float di = rsqrtf((float)g_cursor[node] + 1.0f);
    if (c4 == 0) g_dinv[node] = di;
    float4 v = ((const float4*)g_h1s)[i];
    __half2 h0 = __floats2half2_rn(v.x * di, v.y * di);
    __half2 h1 = __floats2half2_rn(v.z * di, v.w * di);
    unsigned lo = *reinterpret_cast<unsigned*>(&h0);
    unsigned hi = *reinterpret_cast<unsigned*>(&h1);
    uint2 pk = make_uint2(lo, hi);
    *reinterpret_cast<uint2*>(reinterpret_cast<char*>(g_h1h) + (size_t)node * 32 + c4 * 8) = pk;
}

// ---------------- fp16 bucket gather: 2 nodes/warp, 2 lanes/row ----------------
// half-warp lane hl: c2 = hl&1 (16B chunk of the 32B row), g = hl>>1 (row group
// of 8). 8 fp32 accumulators/lane = features c2*8+{0..7} over rows j==g mod 8.
// Full xor-reduction over the 3 group bits (masks 2,4,8 stay within the
// half-warp), then lane hl selects a[hl>>1] = total for f = (hl&1)*8 + (hl>>1).
__device__ __forceinline__ float bucket_gather_h(const __half* __restrict__ tab,
                                                 size_t base, int cnt,
                                                 int lane) {
    int hl = lane & 15;
    int c2 = hl & 1, g = hl >> 1;
    float a[8];
    #pragma unroll
    for (int k = 0; k < 8; k++) a[k] = 0.f;

    #pragma unroll 4
    for (int j = g; j < cnt; j += 8) {
        int s = g_bucket[base + j];
        uint4 t = *reinterpret_cast<const uint4*>(
            reinterpret_cast<const char*>(tab) + (size_t)s * 32 + c2 * 16);
        float2 f0 = __half22float2(*reinterpret_cast<__half2*>(&t.x));
        float2 f1 = __half22float2(*reinterpret_cast<__half2*>(&t.y));
        float2 f2 = __half22float2(*reinterpret_cast<__half2*>(&t.z));
        float2 f3 = __half22float2(*reinterpret_cast<__half2*>(&t.w));
        a[0] += f0.x; a[1] += f0.y; a[2] += f1.x; a[3] += f1.y;
        a[4] += f2.x; a[5] += f2.y; a[6] += f3.x; a[7] += f3.y;
    }

    // reduce each feature accumulator across the 8 row groups
    #pragma unroll
    for (int k = 0; k < 8; k++) {
        a[k] += __shfl_xor_sync(FULL, a[k], 2);
        a[k] += __shfl_xor_sync(FULL, a[k], 4);
        a[k] += __shfl_xor_sync(FULL, a[k], 8);
    }

    // lane hl owns feature f = c2*8 + (hl>>1): select a[hl>>1]
    int sel = hl >> 1;
    float val = a[0];
    if (sel == 1) val = a[1];
    if (sel == 2) val = a[2];
    if (sel == 3) val = a[3];
    if (sel == 4) val = a[4];
    if (sel == 5) val = a[5];
    if (sel == 6) val = a[6];
    if (sel == 7) val = a[7];
    return val;
}

// lane (within half-warp) holding feature j: 2*(j&7) + (j>>3)
#define LANE_OF(j) (2 * ((j) & 7) + ((j) >> 3))

// ---------------- agg1 fused: 2 nodes/warp gather + epilogue -> h2h ----------------
#define AGG_BLK 256
__global__ __launch_bounds__(AGG_BLK) void agg1_k(const float* __restrict__ b1,
                                                  const float* __restrict__ W2, int n) {
    __shared__ float W2s[HIDDEN * NCLS];
    __shared__ float b1s[HIDDEN];
    if (threadIdx.x < HIDDEN * NCLS) W2s[threadIdx.x] = W2[threadIdx.x];
    if (threadIdx.x < HIDDEN) b1s[threadIdx.x] = b1[threadIdx.x];
    __syncthreads();

    int wid = threadIdx.x >> 5, lane = threadIdx.x & 31;
    int half = lane >> 4, hl = lane & 15;
    int v = (blockIdx.x * (AGG_BLK / 32) + wid) * 2 + half;

    int cnt = (v < n) ? min(g_cursor[v], CAP) : 0;
    size_t base = (size_t)v * CAP;
    int f = (hl & 1) * 8 + (hl >> 1);        // feature owned by this lane

    float di = 0.f, self = 0.f;
    if (v < n) {
        di = g_dinv[v];
        self = __half2float(g_h1h[(size_t)v * HIDDEN + f]);   // prescaled
    }

    float val = bucket_gather_h(g_h1h, base, cnt, lane);
    float hr = fmaxf(fmaf(val + self, di, b1s[f]), 0.0f);

    // in-half-warp GEMM2: o[c] = sum_j hrelu[j] * W2[j][c]
    int c = (hl < NCLS) ? hl : 0;
    float o = 0.f;
    #pragma unroll
    for (int j = 0; j < HIDDEN; j++) {
        float hj = __shfl_sync(FULL, hr, (lane & 16) + LANE_OF(j));
        o = fmaf(hj, W2s[j * NCLS + c], o);
    }
    if (v < n)
        g_h2h[(size_t)v * HIDDEN + hl] =
            (hl < NCLS) ? __float2half(o * di) : __float2half(0.0f);
}

// ---------------- agg2: 2 nodes/warp fp16 gather + self, *dinv, +b2 -> out -------
__global__ __launch_bounds__(AGG_BLK) void agg2_k(const float* __restrict__ b2,
                                                  float* __restrict__ out, int n) {
    int wid = threadIdx.x >> 5, lane = threadIdx.x & 31;
    int half = lane >> 4, hl = lane & 15;
    int v = (blockIdx.x * (AGG_BLK / 32) + wid) * 2 + half;

    int cnt = (v < n) ? min(g_cursor[v], CAP) : 0;
    size_t base = (size_t)v * CAP;
    int f = (hl & 1) * 8 + (hl >> 1);

    float di = 0.f, self = 0.f;
    bool valid = (v < n) && (f < NCLS);
    if (valid) {
        di = g_dinv[v];
        self = __half2float(g_h2h[(size_t)v * HIDDEN + f]);
    }

    float val = bucket_gather_h(g_h2h, base, cnt, lane);
    if (valid)
        out[(size_t)v * NCLS + f] = fmaf(val + self, di, b2[f]);
}

// ---------------- launch (fork/join: gemm1 overlaps bucket build) ----------------
extern "C" void kernel_launch(void* const* d_in, const int* in_sizes, int n_in,
                              void* d_out, int out_size) {
    const float* x  = (const float*)d_in[0];
    const void*  ei = d_in[1];
    const float* W1 = (const float*)d_in[2];
    const float* b1 = (const float*)d_in[3];
    const float* W2 = (const float*)d_in[4];
    const float* b2 = (const float*)d_in[5];
    float* out = (float*)d_out;

    int n = in_sizes[0] / F_IN;                 // 100000
    long long E = (long long)in_sizes[1] / 2;   // 3200000

    static cudaStream_t s2 = nullptr;
    static cudaEvent_t evA = nullptr, evB = nullptr;
    static void* cursor_ptr = nullptr;
    if (s2 == nullptr) {   // one-time (outside capture); no allocation
        cudaStreamCreateWithFlags(&s2, cudaStreamNonBlocking);
        cudaEventCreateWithFlags(&evA, cudaEventDisableTiming);
        cudaEventCreateWithFlags(&evB, cudaEventDisableTiming);
        cudaGetSymbolAddress(&cursor_ptr, g_cursor);
    }

    int nb_e2 = (int)((E / 2 + 255) / 256);
    int nb_g1 = (n + G1_BLK - 1) / G1_BLK;
    int nb_ag = (n + 15) / 16;                  // 16 nodes per block
    int nb_s1 = (n * 4 + 255) / 256;

    // fork: gemm1 (x, W1 only) on s2, concurrent with bucket build on default
    cudaEventRecord(evA, 0);
    cudaStreamWaitEvent(s2, evA, 0);
    gemm1_k<<<nb_g1, G1_BLK, 0, s2>>>(x, W1, n);
    cudaEventRecord(evB, s2);

    cudaMemsetAsync(cursor_ptr, 0, (size_t)n * sizeof(int), 0);
    bucket_k<<<nb_e2, 256>>>(ei, E);

    // join, then dependent tail
    cudaStreamWaitEvent(0, evB, 0);
    scale1_k<<<nb_s1, 256>>>(n);
    agg1_k<<<nb_ag, AGG_BLK>>>(b1, W2, n);
    agg2_k<<<nb_ag, AGG_BLK>>>(b2, out, n);
}

// round 14
// speedup vs baseline: 1.0400x; 1.0129x over previous
#include <cuda_runtime.h>
#include <cuda_fp16.h>
#include <cstdint>

#define NN 100000
#define F_IN 512
#define HIDDEN 16
#define NCLS 10
#define CAP 128     // bucket capacity per node; Poisson(32) max-degree ~59 << 128

// ---------------- scratch (no allocation allowed) ----------------
__device__ int   g_cursor[NN];                    // per-node edge count
__device__ float g_dinv[NN];
__device__ int   g_bucket[(size_t)NN * CAP];      // 51.2 MB src lists, stride CAP
__device__ __align__(16) float  g_h1s[(size_t)NN * HIDDEN];   // fp32, unscaled (gemm1 out)
__device__ __align__(16) __half g_h1h[(size_t)NN * HIDDEN];   // fp16, dinv-prescaled
__device__ __align__(16) __half g_h2h[(size_t)NN * HIDDEN];   // fp16, 10 used + 6 zero

#define FULL 0xffffffffu

// inline edge-dtype detect: int64 ids < 2^17 -> odd words zero (uniform loads)
__device__ __forceinline__ int detect_is64(const void* ei) {
    const int* w = (const int*)ei;
    return (w[1] | w[3] | w[5] | w[7]) == 0;
}

// ---------------- single-pass bucket build (2 edges per thread) ----------------
__global__ void bucket_k(const void* __restrict__ ei, long long E) {
    long long e0 = 2LL * ((long long)blockIdx.x * blockDim.x + threadIdx.x);
    if (e0 >= E) return;
    int s0, s1 = 0, d0, d1 = 0;
    int have2 = (e0 + 1 < E);
    if (detect_is64(ei)) {
        const longlong2* p = (const longlong2*)ei;
        longlong2 s = p[e0 >> 1];
        longlong2 d = p[(E + e0) >> 1];
        s0 = (int)s.x; s1 = (int)s.y; d0 = (int)d.x; d1 = (int)d.y;
    } else {
        const int2* p = (const int2*)ei;
        int2 s = p[e0 >> 1];
        int2 d = p[(E + e0) >> 1];
        s0 = s.x; s1 = s.y; d0 = d.x; d1 = d.y;
    }
    int slot0 = atomicAdd(&g_cursor[d0], 1);
    if (slot0 < CAP) g_bucket[(size_t)d0 * CAP + slot0] = s0;
    if (have2) {
        int slot1 = atomicAdd(&g_cursor[d1], 1);
        if (slot1 < CAP) g_bucket[(size_t)d1 * CAP + slot1] = s1;
    }
}

// ---------------- GEMM1 (FFMA2, double-buffered, float4 loads) ----------------
#define G1_BLK 128
#define G1_KC 16
#define G1_NCH (F_IN / G1_KC)   // 32
__global__ __launch_bounds__(G1_BLK) void gemm1_k(const float* __restrict__ x,
                                                  const float* __restrict__ W1, int n) {
    __shared__ __align__(16) float Ws[F_IN * HIDDEN];       // 32 KB
    __shared__ float xs[2][G1_BLK][G1_KC + 1];
    for (int i = threadIdx.x; i < F_IN * HIDDEN; i += G1_BLK) Ws[i] = W1[i];

    int base = blockIdx.x * G1_BLK;
    int node = base + threadIdx.x;

    unsigned long long acc2[8];
    #pragma unroll
    for (int q = 0; q < 8; q++) acc2[q] = 0ULL;

    float4 r[4];
    #pragma unroll
    for (int i = 0; i < 4; i++) {
        int q = threadIdx.x + i * G1_BLK;
        int row = q >> 2, c4 = q & 3;
        int nn = base + row;
        r[i] = (nn < n) ? *(const float4*)(x + (size_t)nn * F_IN + 0 + c4 * 4)
                        : make_float4(0.f, 0.f, 0.f, 0.f);
    }

    int p = 0;
    for (int ch = 0; ch < G1_NCH; ch++) {
        #pragma unroll
        for (int i = 0; i < 4; i++) {
            int q = threadIdx.x + i * G1_BLK;
            int row = q >> 2, c4 = q & 3;
            xs[p][row][c4 * 4 + 0] = r[i].x;
            xs[p][row][c4 * 4 + 1] = r[i].y;
            xs[p][row][c4 * 4 + 2] = r[i].z;
            xs[p][row][c4 * 4 + 3] = r[i].w;
        }
        __syncthreads();
        if (ch + 1 < G1_NCH) {
            int kc = (ch + 1) * G1_KC;
            #pragma unroll
            for (int i = 0; i < 4; i++) {
                int q = threadIdx.x + i * G1_BLK;
                int row = q >> 2, c4 = q & 3;
                int nn = base + row;
                r[i] = (nn < n) ? *(const float4*)(x + (size_t)nn * F_IN + kc + c4 * 4)
                                : make_float4(0.f, 0.f, 0.f, 0.f);
            }
        }
        int kc = ch * G1_KC;
        #pragma unroll
        for (int c = 0; c < G1_KC; c++) {
            float xv = xs[p][threadIdx.x][c];
            unsigned long long xv2;
            asm("mov.b64 %0, {%1, %1};" : "=l"(xv2) : "f"(xv));
            const ulonglong2* w = (const ulonglong2*)&Ws[(kc + c) * HIDDEN];
            ulonglong2 wa = w[0];
            ulonglong2 wb = w[1];
            asm("fma.rn.f32x2 %0, %1, %2, %0;" : "+l"(acc2[0]) : "l"(xv2), "l"(wa.x));
            asm("fma.rn.f32x2 %0, %1, %2, %0;" : "+l"(acc2[1]) : "l"(xv2), "l"(wa.y));
            asm("fma.rn.f32x2 %0, %1, %2, %0;" : "+l"(acc2[2]) : "l"(xv2), "l"(wb.x));
            asm("fma.rn.f32x2 %0, %1, %2, %0;" : "+l"(acc2[3]) : "l"(xv2), "l"(wb.y));
            wa = w[2];
            wb = w[3];
            asm("fma.rn.f32x2 %0, %1, %2, %0;" : "+l"(acc2[4]) : "l"(xv2), "l"(wa.x));
            asm("fma.rn.f32x2 %0, %1, %2, %0;" : "+l"(acc2[5]) : "l"(xv2), "l"(wa.y));
            asm("fma.rn.f32x2 %0, %1, %2, %0;" : "+l"(acc2[6]) : "l"(xv2), "l"(wb.x));
            asm("fma.rn.f32x2 %0, %1, %2, %0;" : "+l"(acc2[7]) : "l"(xv2), "l"(wb.y));
        }
        p ^= 1;
    }
    if (node < n) {
        float4* h = (float4*)(g_h1s + (size_t)node * HIDDEN);
        #pragma unroll
        for (int q = 0; q < 4; q++) {
            float a, b, c, d;
            asm("mov.b64 {%0, %1}, %2;" : "=f"(a), "=f"(b) : "l"(acc2[2 * q]));
            asm("mov.b64 {%0, %1}, %2;" : "=f"(c), "=f"(d) : "l"(acc2[2 * q + 1]));
            h[q] = make_float4(a, b, c, d);
        }
    }
}

// ---------------- scale1: dinv = rsqrt(deg+1); h1h = fp16(h1s * dinv) ----------
__global__ void scale1_k(int n) {
    int i = blockIdx.x * blockDim.x + threadIdx.x;   // one float4 per thread
    if (i >= n * 4) return;
    int node = i >> 2, c4 = i & 3;
    float di = rsqrtf((float)g_cursor[node] + 1.0f);
    if (c4 == 0) g_dinv[node] = di;
    float4 v = ((const float4*)g_h1s)[i];
    __half2 h0 = __floats2half2_rn(v.x * di, v.y * di);
    __half2 h1 = __floats2half2_rn(v.z * di, v.w * di);
    unsigned lo = *reinterpret_cast<unsigned*>(&h0);
    unsigned hi = *reinterpret_cast<unsigned*>(&h1);
    uint2 pk = make_uint2(lo, hi);
    *reinterpret_cast<uint2*>(reinterpret_cast<char*>(g_h1h) + (size_t)node * 32 + c4 * 8) = pk;
}

// ---------------- fp16 bucket gather: 2 nodes/warp, 2 lanes/row, HADD2 accum ----
// half-warp lane hl: c2 = hl&1 (16B chunk of the 32B row), g = hl>>1 (row group
// of 8). 4 half2 accumulators/lane (HADD2; only ~cnt/8 fp16 adds each, then
// fp32 conversion + fp32 cross-lane reduction). h2acc[k] holds the feature pair
// (c2*8+2k, c2*8+2k+1). Full xor-reduction over group bits (2,4,8), then lane
// hl selects the value for its feature f = (hl&1)*8 + (hl>>1).
__device__ __forceinline__ float bucket_gather_h(const __half* __restrict__ tab,
                                                 size_t base, int cnt,
                                                 int lane) {
    int hl = lane & 15;
    int c2 = hl & 1, g = hl >> 1;
    __half2 h2acc[4];
    #pragma unroll
    for (int k = 0; k < 4; k++) h2acc[k] = __floats2half2_rn(0.f, 0.f);

    #pragma unroll 4
    for (int j = g; j < cnt; j += 8) {
        int s = g_bucket[base + j];
        uint4 t = *reinterpret_cast<const uint4*>(
            reinterpret_cast<const char*>(tab) + (size_t)s * 32 + c2 * 16);
        h2acc[0] = __hadd2(h2acc[0], *reinterpret_cast<__half2*>(&t.x));
        h2acc[1] = __hadd2(h2acc[1], *reinterpret_cast<__half2*>(&t.y));
        h2acc[2] = __hadd2(h2acc[2], *reinterpret_cast<__half2*>(&t.z));
        h2acc[3] = __hadd2(h2acc[3], *reinterpret_cast<__half2*>(&t.w));
    }

    float a[8];
    #pragma unroll
    for (int k = 0; k < 4; k++) {
        float2 f = __half22float2(h2acc[k]);
        a[2 * k] = f.x;
        a[2 * k + 1] = f.y;
    }

    // reduce each feature accumulator across the 8 row groups (fp32)
    #pragma unroll
    for (int k = 0; k < 8; k++) {
        a[k] += __shfl_xor_sync(FULL, a[k], 2);
        a[k] += __shfl_xor_sync(FULL, a[k], 4);
        a[k] += __shfl_xor_sync(FULL, a[k], 8);
    }

    // lane hl owns feature f = c2*8 + (hl>>1): select a[hl>>1]
    int sel = hl >> 1;
    float val = a[0];
    if (sel == 1) val = a[1];
    if (sel == 2) val = a[2];
    if (sel == 3) val = a[3];
    if (sel == 4) val = a[4];
    if (sel == 5) val = a[5];
    if (sel == 6) val = a[6];
    if (sel == 7) val = a[7];
    return val;
}

// lane (within half-warp) holding feature j: 2*(j&7) + (j>>3)
#define LANE_OF(j) (2 * ((j) & 7) + ((j) >> 3))

// ---------------- agg1 fused: 2 nodes/warp gather + epilogue -> h2h ----------------
#define AGG_BLK 256
__global__ __launch_bounds__(AGG_BLK) void agg1_k(const float* __restrict__ b1,
                                                  const float* __restrict__ W2, int n) {
    __shared__ float W2s[HIDDEN * NCLS];
    __shared__ float b1s[HIDDEN];
    if (threadIdx.x < HIDDEN * NCLS) W2s[threadIdx.x] = W2[threadIdx.x];
    if (threadIdx.x < HIDDEN) b1s[threadIdx.x] = b1[threadIdx.x];
    __syncthreads();

    int wid = threadIdx.x >> 5, lane = threadIdx.x & 31;
    int half = lane >> 4, hl = lane & 15;
    int v = (blockIdx.x * (AGG_BLK / 32) + wid) * 2 + half;

    int cnt = (v < n) ? min(g_cursor[v], CAP) : 0;
    size_t base = (size_t)v * CAP;
    int f = (hl & 1) * 8 + (hl >> 1);        // feature owned by this lane

    float di = 0.f, self = 0.f;
    if (v < n) {
        di = g_dinv[v];
        self = __half2float(g_h1h[(size_t)v * HIDDEN + f]);   // prescaled
    }

    float val = bucket_gather_h(g_h1h, base, cnt, lane);
    float hr = fmaxf(fmaf(val + self, di, b1s[f]), 0.0f);

    // in-half-warp GEMM2: o[c] = sum_j hrelu[j] * W2[j][c]
    int c = (hl < NCLS) ? hl : 0;
    float o = 0.f;
    #pragma unroll
    for (int j = 0; j < HIDDEN; j++) {
        float hj = __shfl_sync(FULL, hr, (lane & 16) + LANE_OF(j));
        o = fmaf(hj, W2s[j * NCLS + c], o);
    }
    if (v < n)
        g_h2h[(size_t)v * HIDDEN + hl] =
            (hl < NCLS) ? __float2half(o * di) : __float2half(0.0f);
}

// ---------------- agg2: 2 nodes/warp fp16 gather + self, *dinv, +b2 -> out -------
__global__ __launch_bounds__(AGG_BLK) void agg2_k(const float* __restrict__ b2,
                                                  float* __restrict__ out, int n) {
    int wid = threadIdx.x >> 5, lane = threadIdx.x & 31;
    int half = lane >> 4, hl = lane & 15;
    int v = (blockIdx.x * (AGG_BLK / 32) + wid) * 2 + half;

    int cnt = (v < n) ? min(g_cursor[v], CAP) : 0;
    size_t base = (size_t)v * CAP;
    int f = (hl & 1) * 8 + (hl >> 1);

    float di = 0.f, self = 0.f;
    bool valid = (v < n) && (f < NCLS);
    if (valid) {
        di = g_dinv[v];
        self = __half2float(g_h2h[(size_t)v * HIDDEN + f]);
    }

    float val = bucket_gather_h(g_h2h, base, cnt, lane);
    if (valid)
        out[(size_t)v * NCLS + f] = fmaf(val + self, di, b2[f]);
}

// ---------------- launch (fork/join: gemm1 overlaps bucket build) ----------------
extern "C" void kernel_launch(void* const* d_in, const int* in_sizes, int n_in,
                              void* d_out, int out_size) {
    const float* x  = (const float*)d_in[0];
    const void*  ei = d_in[1];
    const float* W1 = (const float*)d_in[2];
    const float* b1 = (const float*)d_in[3];
    const float* W2 = (const float*)d_in[4];
    const float* b2 = (const float*)d_in[5];
    float* out = (float*)d_out;

    int n = in_sizes[0] / F_IN;                 // 100000
    long long E = (long long)in_sizes[1] / 2;   // 3200000

    static cudaStream_t s2 = nullptr;
    static cudaEvent_t evA = nullptr, evB = nullptr;
    static void* cursor_ptr = nullptr;
    if (s2 == nullptr) {   // one-time (outside capture); no allocation
        cudaStreamCreateWithFlags(&s2, cudaStreamNonBlocking);
        cudaEventCreateWithFlags(&evA, cudaEventDisableTiming);
        cudaEventCreateWithFlags(&evB, cudaEventDisableTiming);
        cudaGetSymbolAddress(&cursor_ptr, g_cursor);
    }

    int nb_e2 = (int)((E / 2 + 255) / 256);
    int nb_g1 = (n + G1_BLK - 1) / G1_BLK;
    int nb_ag = (n + 15) / 16;                  // 16 nodes per block
    int nb_s1 = (n * 4 + 255) / 256;

    // fork: gemm1 (x, W1 only) on s2, concurrent with bucket build on default
    cudaEventRecord(evA, 0);
    cudaStreamWaitEvent(s2, evA, 0);
    gemm1_k<<<nb_g1, G1_BLK, 0, s2>>>(x, W1, n);
    cudaEventRecord(evB, s2);

    cudaMemsetAsync(cursor_ptr, 0, (size_t)n * sizeof(int), 0);
    bucket_k<<<nb_e2, 256>>>(ei, E);

    // join, then dependent tail
    cudaStreamWaitEvent(0, evB, 0);
    scale1_k<<<nb_s1, 256>>>(n);
    agg1_k<<<nb_ag, AGG_BLK>>>(b1, W2, n);
    agg2_k<<<nb_ag, AGG_BLK>>>(b2, out, n);
}

// round 15
// speedup vs baseline: 1.0764x; 1.0350x over previous
#include <cuda_runtime.h>
#include <cuda_fp16.h>
#include <cstdint>

#define NN 100000
#define F_IN 512
#define HIDDEN 16
#define NCLS 10
#define CAP 128     // bucket capacity per node; Poisson(32) max-degree ~59 << 128

// ---------------- scratch (no allocation allowed) ----------------
__device__ int   g_cursor[NN];                    // per-node edge count
__device__ float g_dinv[NN];
__device__ int   g_bucket[(size_t)NN * CAP];      // 51.2 MB src lists, stride CAP
__device__ __align__(16) __half g_h1h[(size_t)NN * HIDDEN];   // fp16 h1 (scaled in-place)
__device__ __align__(16) __half g_h2h[(size_t)NN * HIDDEN];   // fp16, 10 used + 6 zero

#define FULL 0xffffffffu

// inline edge-dtype detect: int64 ids < 2^17 -> odd words zero (uniform loads)
__device__ __forceinline__ int detect_is64(const void* ei) {
    const int* w = (const int*)ei;
    return (w[1] | w[3] | w[5] | w[7]) == 0;
}

// ---------------- single-pass bucket build (2 edges per thread, edge range) -----
__global__ void bucket_k(const void* __restrict__ ei, long long E,
                         long long lo, long long hi) {
    long long e0 = lo + 2LL * ((long long)blockIdx.x * blockDim.x + threadIdx.x);
    if (e0 >= hi) return;
    int s0, s1 = 0, d0, d1 = 0;
    int have2 = (e0 + 1 < hi);
    if (detect_is64(ei)) {
        const longlong2* p = (const longlong2*)ei;
        longlong2 s = p[e0 >> 1];
        longlong2 d = p[(E + e0) >> 1];
        s0 = (int)s.x; s1 = (int)s.y; d0 = (int)d.x; d1 = (int)d.y;
    } else {
        const int2* p = (const int2*)ei;
        int2 s = p[e0 >> 1];
        int2 d = p[(E + e0) >> 1];
        s0 = s.x; s1 = s.y; d0 = d.x; d1 = d.y;
    }
    int slot0 = atomicAdd(&g_cursor[d0], 1);
    if (slot0 < CAP) g_bucket[(size_t)d0 * CAP + slot0] = s0;
    if (have2) {
        int slot1 = atomicAdd(&g_cursor[d1], 1);
        if (slot1 < CAP) g_bucket[(size_t)d1 * CAP + slot1] = s1;
    }
}

// ---------------- dinv from final counts ----------------
__global__ void dinv_k(int n) {
    int i = blockIdx.x * blockDim.x + threadIdx.x;
    if (i < n) g_dinv[i] = rsqrtf((float)g_cursor[i] + 1.0f);
}

// ---------------- GEMM1 (FFMA2, double-buffered) -> fp16 h1u (unscaled) ---------
#define G1_BLK 128
#define G1_KC 16
#define G1_NCH (F_IN / G1_KC)   // 32
__global__ __launch_bounds__(G1_BLK) void gemm1_k(const float* __restrict__ x,
                                                  const float* __restrict__ W1, int n) {
    __shared__ __align__(16) float Ws[F_IN * HIDDEN];       // 32 KB
    __shared__ float xs[2][G1_BLK][G1_KC + 1];
    for (int i = threadIdx.x; i < F_IN * HIDDEN; i += G1_BLK) Ws[i] = W1[i];

    int base = blockIdx.x * G1_BLK;
    int node = base + threadIdx.x;

    unsigned long long acc2[8];
    #pragma unroll
    for (int q = 0; q < 8; q++) acc2[q] = 0ULL;

    float4 r[4];
    #pragma unroll
    for (int i = 0; i < 4; i++) {
        int q = threadIdx.x + i * G1_BLK;
        int row = q >> 2, c4 = q & 3;
        int nn = base + row;
        r[i] = (nn < n) ? *(const float4*)(x + (size_t)nn * F_IN + 0 + c4 * 4)
                        : make_float4(0.f, 0.f, 0.f, 0.f);
    }

    int p = 0;
    for (int ch = 0; ch < G1_NCH; ch++) {
        #pragma unroll
        for (int i = 0; i < 4; i++) {
            int q = threadIdx.x + i * G1_BLK;
            int row = q >> 2, c4 = q & 3;
            xs[p][row][c4 * 4 + 0] = r[i].x;
            xs[p][row][c4 * 4 + 1] = r[i].y;
            xs[p][row][c4 * 4 + 2] = r[i].z;
            xs[p][row][c4 * 4 + 3] = r[i].w;
        }
        __syncthreads();
        if (ch + 1 < G1_NCH) {
            int kc = (ch + 1) * G1_KC;
            #pragma unroll
            for (int i = 0; i < 4; i++) {
                int q = threadIdx.x + i * G1_BLK;
                int row = q >> 2, c4 = q & 3;
                int nn = base + row;
                r[i] = (nn < n) ? *(const float4*)(x + (size_t)nn * F_IN + kc + c4 * 4)
                                : make_float4(0.f, 0.f, 0.f, 0.f);
            }
        }
        int kc = ch * G1_KC;
        #pragma unroll
        for (int c = 0; c < G1_KC; c++) {
            float xv = xs[p][threadIdx.x][c];
            unsigned long long xv2;
            asm("mov.b64 %0, {%1, %1};" : "=l"(xv2) : "f"(xv));
            const ulonglong2* w = (const ulonglong2*)&Ws[(kc + c) * HIDDEN];
            ulonglong2 wa = w[0];
            ulonglong2 wb = w[1];
            asm("fma.rn.f32x2 %0, %1, %2, %0;" : "+l"(acc2[0]) : "l"(xv2), "l"(wa.x));
            asm("fma.rn.f32x2 %0, %1, %2, %0;" : "+l"(acc2[1]) : "l"(xv2), "l"(wa.y));
            asm("fma.rn.f32x2 %0, %1, %2, %0;" : "+l"(acc2[2]) : "l"(xv2), "l"(wb.x));
            asm("fma.rn.f32x2 %0, %1, %2, %0;" : "+l"(acc2[3]) : "l"(xv2), "l"(wb.y));
            wa = w[2];
            wb = w[3];
            asm("fma.rn.f32x2 %0, %1, %2, %0;" : "+l"(acc2[4]) : "l"(xv2), "l"(wa.x));
            asm("fma.rn.f32x2 %0, %1, %2, %0;" : "+l"(acc2[5]) : "l"(xv2), "l"(wa.y));
            asm("fma.rn.f32x2 %0, %1, %2, %0;" : "+l"(acc2[6]) : "l"(xv2), "l"(wb.x));
            asm("fma.rn.f32x2 %0, %1, %2, %0;" : "+l"(acc2[7]) : "l"(xv2), "l"(wb.y));
        }
        p ^= 1;
    }
    if (node < n) {
        unsigned hp[8];
        #pragma unroll
        for (int q = 0; q < 8; q++) {
            float a, b;
            asm("mov.b64 {%0, %1}, %2;" : "=f"(a), "=f"(b) : "l"(acc2[q]));
            __half2 h = __floats2half2_rn(a, b);
            hp[q] = *reinterpret_cast<unsigned*>(&h);
        }
        uint4* dst = reinterpret_cast<uint4*>(
            reinterpret_cast<char*>(g_h1h) + (size_t)node * 32);
        dst[0] = make_uint4(hp[0], hp[1], hp[2], hp[3]);
        dst[1] = make_uint4(hp[4], hp[5], hp[6], hp[7]);
    }
}

// ---------------- scale1: h1h *= dinv (in-place fp16, join point) ----------------
__global__ void scale1_k(int n) {
    int i = blockIdx.x * blockDim.x + threadIdx.x;   // one uint2 (4 halves) per thread
    if (i >= n * 4) return;
    int node = i >> 2;
    float di = g_dinv[node];
    uint2* ptr = reinterpret_cast<uint2*>(reinterpret_cast<char*>(g_h1h) + (size_t)i * 8);
    uint2 pk = *ptr;
    float2 f0 = __half22float2(*reinterpret_cast<__half2*>(&pk.x));
    float2 f1 = __half22float2(*reinterpret_cast<__half2*>(&pk.y));
    __half2 h0 = __floats2half2_rn(f0.x * di, f0.y * di);
    __half2 h1 = __floats2half2_rn(f1.x * di, f1.y * di);
    *ptr = make_uint2(*reinterpret_cast<unsigned*>(&h0), *reinterpret_cast<unsigned*>(&h1));
}

// ---------------- fp16 bucket gather: 2 nodes/warp, 2 lanes/row, HADD2 accum ----
__device__ __forceinline__ float bucket_gather_h(const __half* __restrict__ tab,
                                                 size_t base, int cnt,
                                                 int lane) {
    int hl = lane & 15;
    int c2 = hl & 1, g = hl >> 1;
    __half2 h2acc[4];
    #pragma unroll
    for (int k = 0; k < 4; k++) h2acc[k] = __floats2half2_rn(0.f, 0.f);

    #pragma unroll 4
    for (int j = g; j < cnt; j += 8) {
        int s = g_bucket[base + j];
        uint4 t = *reinterpret_cast<const uint4*>(
            reinterpret_cast<const char*>(tab) + (size_t)s * 32 + c2 * 16);
        h2acc[0] = __hadd2(h2acc[0], *reinterpret_cast<__half2*>(&t.x));
        h2acc[1] = __hadd2(h2acc[1], *reinterpret_cast<__half2*>(&t.y));
        h2acc[2] = __hadd2(h2acc[2], *reinterpret_cast<__half2*>(&t.z));
        h2acc[3] = __hadd2(h2acc[3], *reinterpret_cast<__half2*>(&t.w));
    }

    float a[8];
    #pragma unroll
    for (int k = 0; k < 4; k++) {
        float2 f = __half22float2(h2acc[k]);
        a[2 * k] = f.x;
        a[2 * k + 1] = f.y;
    }

    #pragma unroll
    for (int k = 0; k < 8; k++) {
        a[k] += __shfl_xor_sync(FULL, a[k], 2);
        a[k] += __shfl_xor_sync(FULL, a[k], 4);
        a[k] += __shfl_xor_sync(FULL, a[k], 8);
    }

    int sel = hl >> 1;
    float val = a[0];
    if (sel == 1) val = a[1];
    if (sel == 2) val = a[2];
    if (sel == 3) val = a[3];
    if (sel == 4) val = a[4];
    if (sel == 5) val = a[5];
    if (sel == 6) val = a[6];
    if (sel == 7) val = a[7];
    return val;
}

// lane (within half-warp) holding feature j: 2*(j&7) + (j>>3)
#define LANE_OF(j) (2 * ((j) & 7) + ((j) >> 3))

// ---------------- agg1 fused: 2 nodes/warp gather + epilogue -> h2h ----------------
#define AGG_BLK 256
__global__ __launch_bounds__(AGG_BLK) void agg1_k(const float* __restrict__ b1,
                                                  const float* __restrict__ W2, int n) {
    __shared__ float W2s[HIDDEN * NCLS];
    __shared__ float b1s[HIDDEN];
    if (threadIdx.x < HIDDEN * NCLS) W2s[threadIdx.x] = W2[threadIdx.x];
    if (threadIdx.x < HIDDEN) b1s[threadIdx.x] = b1[threadIdx.x];
    __syncthreads();

    int wid = threadIdx.x >> 5, lane = threadIdx.x & 31;
    int half = lane >> 4, hl = lane & 15;
    int v = (blockIdx.x * (AGG_BLK / 32) + wid) * 2 + half;

    int cnt = (v < n) ? min(g_cursor[v], CAP) : 0;
    size_t base = (size_t)v * CAP;
    int f = (hl & 1) * 8 + (hl >> 1);        // feature owned by this lane

    float di = 0.f, self = 0.f;
    if (v < n) {
        di = g_dinv[v];
        self = __half2float(g_h1h[(size_t)v * HIDDEN + f]);   // prescaled
    }

    float val = bucket_gather_h(g_h1h, base, cnt, lane);
    float hr = fmaxf(fmaf(val + self, di, b1s[f]), 0.0f);

    // in-half-warp GEMM2: o[c] = sum_j hrelu[j] * W2[j][c]
    int c = (hl < NCLS) ? hl : 0;
    float o = 0.f;
    #pragma unroll
    for (int j = 0; j < HIDDEN; j++) {
        float hj = __shfl_sync(FULL, hr, (lane & 16) + LANE_OF(j));
        o = fmaf(hj, W2s[j * NCLS + c], o);
    }
    if (v < n)
        g_h2h[(size_t)v * HIDDEN + hl] =
            (hl < NCLS) ? __float2half(o * di) : __float2half(0.0f);
}

// ---------------- agg2: 2 nodes/warp fp16 gather + self, *dinv, +b2 -> out -------
__global__ __launch_bounds__(AGG_BLK) void agg2_k(const float* __restrict__ b2,
                                                  float* __restrict__ out, int n) {
    int wid = threadIdx.x >> 5, lane = threadIdx.x & 31;
    int half = lane >> 4, hl = lane & 15;
    int v = (blockIdx.x * (AGG_BLK / 32) + wid) * 2 + half;

    int cnt = (v < n) ? min(g_cursor[v], CAP) : 0;
    size_t base = (size_t)v * CAP;
    int f = (hl & 1) * 8 + (hl >> 1);

    float di = 0.f, self = 0.f;
    bool valid = (v < n) && (f < NCLS);
    if (valid) {
        di = g_dinv[v];
        self = __half2float(g_h2h[(size_t)v * HIDDEN + f]);
    }

    float val = bucket_gather_h(g_h2h, base, cnt, lane);
    if (valid)
        out[(size_t)v * NCLS + f] = fmaf(val + self, di, b2[f]);
}

// ---------------- launch (fork/join; gemm1 = 4th submission for ncu) -------------
extern "C" void kernel_launch(void* const* d_in, const int* in_sizes, int n_in,
                              void* d_out, int out_size) {
    const float* x  = (const float*)d_in[0];
    const void*  ei = d_in[1];
    const float* W1 = (const float*)d_in[2];
    const float* b1 = (const float*)d_in[3];
    const float* W2 = (const float*)d_in[4];
    const float* b2 = (const float*)d_in[5];
    float* out = (float*)d_out;

    int n = in_sizes[0] / F_IN;                 // 100000
    long long E = (long long)in_sizes[1] / 2;   // 3200000

    static cudaStream_t s2 = nullptr;
    static cudaEvent_t evA = nullptr, evB = nullptr;
    static void* cursor_ptr = nullptr;
    if (s2 == nullptr) {   // one-time (outside capture); no allocation
        cudaStreamCreateWithFlags(&s2, cudaStreamNonBlocking);
        cudaEventCreateWithFlags(&evA, cudaEventDisableTiming);
        cudaEventCreateWithFlags(&evB, cudaEventDisableTiming);
        cudaGetSymbolAddress(&cursor_ptr, g_cursor);
    }

    long long Eh = (E / 4) * 2;                 // even split point
    int nb_eA = (int)(((Eh + 1) / 2 + 255) / 256);
    int nb_eB = (int)((((E - Eh) + 1) / 2 + 255) / 256);
    int nb_n  = (n + 255) / 256;
    int nb_g1 = (n + G1_BLK - 1) / G1_BLK;
    int nb_ag = (n + 15) / 16;                  // 16 nodes per block
    int nb_s1 = (n * 4 + 255) / 256;

    // fork marker: gemm1 depends only on graph root
    cudaEventRecord(evA, 0);
    cudaStreamWaitEvent(s2, evA, 0);

    cudaMemsetAsync(cursor_ptr, 0, (size_t)n * sizeof(int), 0);
    bucket_k<<<nb_eA, 256>>>(ei, E, 0, Eh);         // kernel 1
    bucket_k<<<nb_eB, 256>>>(ei, E, Eh, E);         // kernel 2
    dinv_k<<<nb_n, 256>>>(n);                       // kernel 3
    gemm1_k<<<nb_g1, G1_BLK, 0, s2>>>(x, W1, n);    // kernel 4 (profiled slot)
    cudaEventRecord(evB, s2);

    // join, then dependent tail
    cudaStreamWaitEvent(0, evB, 0);
    scale1_k<<<nb_s1, 256>>>(n);                    // needs gemm1 + dinv
    agg1_k<<<nb_ag, AGG_BLK>>>(b1, W2, n);
    agg2_k<<<nb_ag, AGG_BLK>>>(b2, out, n);
}